// round 2
// baseline (speedup 1.0000x reference)
#include <cuda_runtime.h>
#include <cstdint>
#include <cstddef>

// Problem constants
#define NROWS 65536   // 64*32*32 flat rows
#define KC    1024    // codes
#define DIM   256     // embedding dim
#define HW    1024    // 32*32
#define BATCH 64

// Output packing (tuple order, all float32):
//   z_q_st [16777216], commit_loss [1], indices [65536],
//   new_cb [262144], new_cs [1024], new_dw [262144]
#define OUT_ZQ   0ull
#define OUT_LOSS 16777216ull
#define OUT_IDX  16777217ull
#define OUT_CB   16842753ull
#define OUT_CS   17104897ull
#define OUT_DW   17105921ull

// Scratch (device globals: no allocations allowed)
__device__ float  g_c2[KC];        // sum(cb*cb) per code, sequential-order fp32
__device__ float  g_f2[NROWS];     // sum(flat*flat) per row, sequential-order fp32
__device__ int    g_idx[NROWS];
__device__ int    g_counts[KC];
__device__ float  g_dw[KC * DIM];
__device__ double g_loss;
__device__ int    g_rand[KC];
__device__ float  g_smooth[KC];
__device__ int    g_dead[KC];

// ---------------------------------------------------------------------------
__global__ void k_init() {
    int i = blockIdx.x * blockDim.x + threadIdx.x;   // 1024*256 = 262144
    if (i < KC * DIM) g_dw[i] = 0.0f;
    if (i < KC)       g_counts[i] = 0;
    if (i == 0)       g_loss = 0.0;
}

// ---------------------------------------------------------------------------
// c2[k] = sum_d fl(cb[k][d]^2), accumulated sequentially in-order fp32
// (emulates XLA CPU naive reduce: no fma, no reassociation)
__global__ void k_c2(const float* __restrict__ cb) {
    int k = blockIdx.x * blockDim.x + threadIdx.x;   // 4*256
    if (k >= KC) return;
    const float* row = cb + (size_t)k * DIM;
    float s = 0.0f;
    for (int d = 0; d < DIM; ++d) {
        float v = row[d];
        s = __fadd_rn(s, __fmul_rn(v, v));
    }
    g_c2[k] = s;
}

// ---------------------------------------------------------------------------
// f2[n] = sum_d fl(flat[n][d]^2) sequential in-order fp32.
// flat[n][d] = z[b][d][hw], n = b*1024+hw. Loads coalesced across threads.
__global__ void __launch_bounds__(256) k_f2(const float* __restrict__ z) {
    int n = blockIdx.x * 256 + threadIdx.x;          // 256 blocks
    int b = n >> 10, hw = n & 1023;
    const float* p = z + (size_t)b * DIM * HW + hw;
    float acc = 0.0f;
#pragma unroll 8
    for (int d = 0; d < DIM; ++d) {
        float v = p[(size_t)d * HW];
        acc = __fadd_rn(acc, __fmul_rn(v, v));
    }
    g_f2[n] = acc;
}

// ---------------------------------------------------------------------------
// Exact JAX threefry2x32 for key(1):
//   jax.random.randint(key(1), (1024,), 0, 65536) == threefry_bits & 0xFFFF
__device__ __forceinline__ uint32_t tf_rotl(uint32_t v, int r) {
    return (v << r) | (v >> (32 - r));
}
__global__ void k_rng() {
    int i = threadIdx.x;                 // 512 threads
    if (i >= 512) return;
    const uint32_t ks0 = 0u, ks1 = 1u, ks2 = 0x1BD11BDBu;
    uint32_t x0 = (uint32_t)i + ks0;
    uint32_t x1 = (uint32_t)(i + 512) + ks1;
    const int ra[4] = {13, 15, 26, 6};
    const int rb[4] = {17, 29, 16, 24};
#define TF_R4(rots) { x0 += x1; x1 = tf_rotl(x1, rots[0]); x1 ^= x0; \
                      x0 += x1; x1 = tf_rotl(x1, rots[1]); x1 ^= x0; \
                      x0 += x1; x1 = tf_rotl(x1, rots[2]); x1 ^= x0; \
                      x0 += x1; x1 = tf_rotl(x1, rots[3]); x1 ^= x0; }
    TF_R4(ra); x0 += ks1; x1 += ks2 + 1u;
    TF_R4(rb); x0 += ks2; x1 += ks0 + 2u;
    TF_R4(ra); x0 += ks0; x1 += ks1 + 3u;
    TF_R4(rb); x0 += ks1; x1 += ks2 + 4u;
    TF_R4(ra); x0 += ks2; x1 += ks0 + 5u;
#undef TF_R4
    g_rand[i]       = (int)(x0 & 0xFFFFu);
    g_rand[i + 512] = (int)(x1 & 0xFFFFu);
}

// ---------------------------------------------------------------------------
// Argmin kernel emulating the reference's fp32 rounding chain:
//   r[n,k]  = fp32 fma chain over d ascending (Eigen gebp order)
//   d2[n,k] = fl( fl(f2[n] - 2*r) + c2[k] )
//   argmin with ties -> lowest k
#define SMEM_ARGMIN ((64 * 256 + 64 * 260) * 4)
__global__ void __launch_bounds__(256) k_argmin(const float* __restrict__ z,
                                                const float* __restrict__ cb) {
    extern __shared__ float sm[];
    float* s_flat = sm;              // 64 rows x 256 (XOR-swizzled float4 slots)
    float* s_code = sm + 64 * 256;   // 64 codes x 260 (pad 4)

    const int tid = threadIdx.x;
    const int n0  = blockIdx.x * 64;
    const int b   = n0 >> 10;
    const int hw0 = n0 & 1023;
    const float* zb = z + (size_t)b * DIM * HW + hw0;

    // Load flat tile (coalesced over r=hw), swizzle float4 slot by (r>>2)
    {
        int r = tid & 63;
        int dbase = tid >> 6;   // 0..3
        int rh = r >> 2;
#pragma unroll
        for (int i = 0; i < 64; ++i) {
            int d = i * 4 + dbase;
            float v = zb[(size_t)d * HW + r];
            int slot = (d >> 2) ^ rh;
            s_flat[r * 256 + slot * 4 + (d & 3)] = v;
        }
    }

    const int q  = tid & 15;       // row-group
    const int g  = tid >> 4;       // code-group 0..15
    const int r0 = q * 4;
    const int c0 = g * 4;

    float f2v[4];
#pragma unroll
    for (int a = 0; a < 4; ++a) f2v[a] = g_f2[n0 + r0 + a];

    float best[4];
    int   bk[4];
#pragma unroll
    for (int a = 0; a < 4; ++a) { best[a] = 3.4e38f; bk[a] = 0; }

    for (int t = 0; t < 16; ++t) {
        __syncthreads();
        {
            const float* cbt = cb + (size_t)(t * 64) * DIM;
#pragma unroll
            for (int i = 0; i < 64; ++i)
                s_code[i * 260 + tid] = cbt[i * 256 + tid];
        }
        __syncthreads();

        float acc[4][4];
#pragma unroll
        for (int a = 0; a < 4; ++a)
#pragma unroll
            for (int c = 0; c < 4; ++c) acc[a][c] = 0.0f;

        // fp32 fma chain, d ascending, single accumulator per (row,code):
        // bitwise-matches a sequential-k fma accumulation.
#pragma unroll 4
        for (int d4 = 0; d4 < 64; ++d4) {
            int sf = d4 ^ q;
            float4 fa[4], cc[4];
#pragma unroll
            for (int a = 0; a < 4; ++a)
                fa[a] = *(const float4*)(s_flat + (r0 + a) * 256 + sf * 4);
#pragma unroll
            for (int c = 0; c < 4; ++c)
                cc[c] = *(const float4*)(s_code + (c0 + c) * 260 + d4 * 4);
#pragma unroll
            for (int a = 0; a < 4; ++a)
#pragma unroll
                for (int c = 0; c < 4; ++c) {
                    acc[a][c] = __fmaf_rn(fa[a].x, cc[c].x, acc[a][c]);
                    acc[a][c] = __fmaf_rn(fa[a].y, cc[c].y, acc[a][c]);
                    acc[a][c] = __fmaf_rn(fa[a].z, cc[c].z, acc[a][c]);
                    acc[a][c] = __fmaf_rn(fa[a].w, cc[c].w, acc[a][c]);
                }
        }

#pragma unroll
        for (int c = 0; c < 4; ++c) {
            int k = t * 64 + c0 + c;
            float c2k = g_c2[k];
#pragma unroll
            for (int a = 0; a < 4; ++a) {
                // reference rounding chain: (f2 - 2r) + c2, each step fp32
                float d2 = __fadd_rn(__fsub_rn(f2v[a], 2.0f * acc[a][c]), c2k);
                // k ascending within this thread: strict < keeps lowest k on ties
                if (d2 < best[a]) { best[a] = d2; bk[a] = k; }
            }
        }
    }

    // cross-thread reduce per row (16 code-groups per row), ties -> lower k
    __syncthreads();
    float* rs = s_code;                       // 64 x 16 floats
    int*   rk = (int*)(s_code + 64 * 16);     // 64 x 16 ints
#pragma unroll
    for (int a = 0; a < 4; ++a) {
        rs[(r0 + a) * 16 + g] = best[a];
        rk[(r0 + a) * 16 + g] = bk[a];
    }
    __syncthreads();
    if (tid < 64) {
        float bs = 3.4e38f; int bkk = 1 << 30;
        for (int gg = 0; gg < 16; ++gg) {
            float s = rs[tid * 16 + gg];
            int   k = rk[tid * 16 + gg];
            if (s < bs || (s == bs && k < bkk)) { bs = s; bkk = k; }
        }
        g_idx[n0 + tid] = bkk;
        atomicAdd(&g_counts[bkk], 1);
    }
}

// ---------------------------------------------------------------------------
// z_q output (NCHW), indices output, commit-loss partial, dw scatter
__global__ void __launch_bounds__(256) k_scatter(const float* __restrict__ z,
                                                 const float* __restrict__ cb,
                                                 float* __restrict__ out,
                                                 size_t osz) {
    int n  = blockIdx.x * 256 + threadIdx.x;   // 256 blocks
    int b  = n >> 10, hw = n & 1023;
    int k  = g_idx[n];
    if (OUT_IDX + (size_t)n < osz) out[OUT_IDX + n] = (float)k;

    const float*  zr   = z  + (size_t)b * DIM * HW + hw;
    float*        orow = out + OUT_ZQ + (size_t)b * DIM * HW + hw;
    const float4* cr   = (const float4*)(cb + (size_t)k * DIM);
    float*        dwr  = g_dw + (size_t)k * DIM;

    float ls = 0.0f;
#pragma unroll 4
    for (int d4 = 0; d4 < 64; ++d4) {
        float4 qv = cr[d4];
        int d = d4 * 4;
        float z0 = zr[(size_t)(d + 0) * HW];
        float z1 = zr[(size_t)(d + 1) * HW];
        float z2 = zr[(size_t)(d + 2) * HW];
        float z3 = zr[(size_t)(d + 3) * HW];
        orow[(size_t)(d + 0) * HW] = qv.x;
        orow[(size_t)(d + 1) * HW] = qv.y;
        orow[(size_t)(d + 2) * HW] = qv.z;
        orow[(size_t)(d + 3) * HW] = qv.w;
        float e0 = qv.x - z0, e1 = qv.y - z1, e2 = qv.z - z2, e3 = qv.w - z3;
        ls = fmaf(e0, e0, ls); ls = fmaf(e1, e1, ls);
        ls = fmaf(e2, e2, ls); ls = fmaf(e3, e3, ls);
        atomicAdd(&dwr[d + 0], z0);
        atomicAdd(&dwr[d + 1], z1);
        atomicAdd(&dwr[d + 2], z2);
        atomicAdd(&dwr[d + 3], z3);
    }

    for (int o = 16; o > 0; o >>= 1) ls += __shfl_down_sync(0xffffffffu, ls, o);
    __shared__ float ws[8];
    int lane = threadIdx.x & 31, w = threadIdx.x >> 5;
    if (lane == 0) ws[w] = ls;
    __syncthreads();
    if (threadIdx.x == 0) {
        float s = 0.0f;
#pragma unroll
        for (int i = 0; i < 8; ++i) s += ws[i];
        atomicAdd(&g_loss, (double)s);
    }
}

// ---------------------------------------------------------------------------
__global__ void k_fin_a(const float* __restrict__ ema_cs,
                        float* __restrict__ out, size_t osz) {
    int k = threadIdx.x;   // 1024 threads, 1 block
    float cs = __fadd_rn(__fmul_rn(0.99f, ema_cs[k]),
                         __fmul_rn(0.01f, (float)g_counts[k]));
    __shared__ float red[1024];
    red[k] = cs;
    __syncthreads();
    for (int o = 512; o > 0; o >>= 1) {
        if (k < o) red[k] += red[k + o];
        __syncthreads();
    }
    float n = red[0];
    float smv = (cs + 1e-5f) / (n + 1024.0f * 1e-5f) * n;
    g_smooth[k] = smv;
    int dead = cs < 1.0f;
    g_dead[k] = dead;
    if (OUT_CS + (size_t)k < osz) out[OUT_CS + k] = dead ? 1.0f : cs;
    if (k == 0 && OUT_LOSS < osz)
        out[OUT_LOSS] = (float)(0.5 * g_loss / 16777216.0);
}

// ---------------------------------------------------------------------------
__global__ void k_fin_b(const float* __restrict__ ema_dw,
                        const float* __restrict__ z,
                        float* __restrict__ out, size_t osz) {
    int k = blockIdx.x;      // 1024
    int d = threadIdx.x;     // 256
    size_t e = (size_t)k * DIM + d;
    float dwe = __fadd_rn(__fmul_rn(0.99f, ema_dw[e]),
                          __fmul_rn(0.01f, g_dw[e]));
    float cbv = dwe / g_smooth[k];
    if (g_dead[k]) {
        int r = g_rand[k];
        int rb = r >> 10, rhw = r & 1023;
        float rr = z[((size_t)rb * DIM + d) * HW + rhw];
        cbv = rr;
        dwe = rr;
    }
    if (OUT_CB + e < osz) out[OUT_CB + e] = cbv;
    if (OUT_DW + e < osz) out[OUT_DW + e] = dwe;
}

// ---------------------------------------------------------------------------
extern "C" void kernel_launch(void* const* d_in, const int* in_sizes, int n_in,
                              void* d_out, int out_size) {
    const float* z      = (const float*)d_in[0];  // [64,256,32,32]
    const float* cb     = (const float*)d_in[1];  // [1024,256]
    const float* ema_cs = (const float*)d_in[2];  // [1024]
    const float* ema_dw = (const float*)d_in[3];  // [1024,256]
    float* out = (float*)d_out;
    size_t osz = (size_t)out_size;

    cudaFuncSetAttribute(k_argmin, cudaFuncAttributeMaxDynamicSharedMemorySize,
                         SMEM_ARGMIN);

    k_init<<<1024, 256>>>();
    k_c2<<<4, 256>>>(cb);
    k_f2<<<256, 256>>>(z);
    k_rng<<<1, 512>>>();
    k_argmin<<<1024, 256, SMEM_ARGMIN>>>(z, cb);
    k_scatter<<<256, 256>>>(z, cb, out, osz);
    k_fin_a<<<1, 1024>>>(ema_cs, out, osz);
    k_fin_b<<<1024, 256>>>(ema_dw, z, out, osz);
}